// round 16
// baseline (speedup 1.0000x reference)
#include <cuda_runtime.h>
#include <cuda_fp16.h>
#include <math.h>
#include <stdint.h>

// ---------------- problem constants ----------------
#define NB    64
#define NSEQ  198
#define NTOK  (NB*NSEQ)      // 12672
#define NPAT  (NB*196)       // 12544
#define CDIM  768
#define NHEAD 12
#define HD    64

// weight fp16 pool offsets (elements)
#define W_PATCH 0
#define W_QKV   589824
#define W_PROJ  21823488
#define W_FC1   28901376
#define W_FC2   57212928
#define W_TOTAL 85524480

// ---------------- scratch ----------------
__device__ float  g_t   [(size_t)NTOK*CDIM];
__device__ float  g_mask[(size_t)12*NB*NSEQ];
__device__ float  g_sfeat[(size_t)NB*6912];
__device__ __half g_ah  [(size_t)NTOK*CDIM];
__device__ __half g_qkvh[(size_t)NTOK*3*CDIM];
__device__ __half g_oh  [(size_t)NTOK*CDIM];
__device__ __half g_hh  [(size_t)NTOK*4*CDIM];
__device__ __half g_wh  [(size_t)W_TOTAL];

enum { EP_NONE=0, EP_BIAS=1, EP_BIAS_RES=2, EP_BIAS_GELU=3, EP_PATCH=4 };

// ---------------- helpers ----------------
__device__ __forceinline__ uint32_t smem_u32(const void* p){
    uint32_t a;
    asm("{ .reg .u64 t; cvta.to.shared.u64 t, %1; cvt.u32.u64 %0, t; }" : "=r"(a) : "l"(p));
    return a;
}
__device__ __forceinline__ void mma_fp16(float c[4], const unsigned a[4], const unsigned b[2]){
    asm volatile("mma.sync.aligned.m16n8k16.row.col.f32.f16.f16.f32 "
        "{%0,%1,%2,%3}, {%4,%5,%6,%7}, {%8,%9}, {%0,%1,%2,%3};\n"
        : "+f"(c[0]),"+f"(c[1]),"+f"(c[2]),"+f"(c[3])
        : "r"(a[0]),"r"(a[1]),"r"(a[2]),"r"(a[3]), "r"(b[0]),"r"(b[1]));
}
__device__ __forceinline__ void ldsm_x4(unsigned r[4], uint32_t a){
    asm volatile("ldmatrix.sync.aligned.m8n8.x4.shared.b16 {%0,%1,%2,%3}, [%4];"
        : "=r"(r[0]),"=r"(r[1]),"=r"(r[2]),"=r"(r[3]) : "r"(a));
}
__device__ __forceinline__ void cp16(uint32_t s, const void* g){
    asm volatile("cp.async.cg.shared.global [%0], [%1], 16;" :: "r"(s), "l"(g));
}
#define CP_COMMIT() asm volatile("cp.async.commit_group;" ::: "memory")
#define CP_WAIT(n)  asm volatile("cp.async.wait_group %0;" :: "n"(n) : "memory")

// ---------------- merged f32 -> f16 convert ----------------
#define R_PATCH 147456
#define R_QKV   (R_PATCH + 5308416)
#define R_PROJ  (R_QKV + 1769472)
#define R_FC1   (R_PROJ + 7077888)
#define R_FC2   (R_FC1 + 7077888)
__global__ void f2h_all(const float* __restrict__ pw, const float* __restrict__ qw,
                        const float* __restrict__ prw, const float* __restrict__ f1w,
                        const float* __restrict__ f2w, __half* __restrict__ dst)
{
    int i = blockIdx.x*256 + threadIdx.x;
    if (i >= R_FC2) return;
    const float* src;
    int off;
    if (i < R_PATCH)      { src = pw;  off = i; }
    else if (i < R_QKV)   { src = qw;  off = i - R_PATCH; }
    else if (i < R_PROJ)  { src = prw; off = i - R_QKV; }
    else if (i < R_FC1)   { src = f1w; off = i - R_PROJ; }
    else                  { src = f2w; off = i - R_FC1; }
    float4 v = ((const float4*)src)[off];
    ((__half2*)dst)[(size_t)i*2  ] = __floats2half2_rn(v.x, v.y);
    ((__half2*)dst)[(size_t)i*2+1] = __floats2half2_rn(v.z, v.w);
}

// ---------------- pipelined fp16 GEMM-NT (round-12 proven schedule) ----------------
#define GSTAGES      4
#define GSTAGE_BYTES 20480
#define G_SMEM       (GSTAGES*GSTAGE_BYTES)   // 81920
template<int EPI, typename OT>
__global__ void __launch_bounds__(256,2) gemm_h2(
    const __half* __restrict__ A, const __half* __restrict__ B,
    const float* __restrict__ bias, const float* __restrict__ res,
    OT* __restrict__ C, int M, int N, int K)
{
    extern __shared__ char smem[];
    const uint32_t sb = smem_u32(smem);
    const int tid=threadIdx.x, warp=tid>>5, lane=tid&31;
    const int wm=warp>>1, wn=warp&1;
    const int gid=lane>>2, tg=lane&3;
    const int bm=blockIdx.y*128, bn=blockIdx.x*128;

    const int lrow = tid>>2, lseg = tid&3;
    const __half* Ag = A + (size_t)(bm+lrow)*K + lseg*8;
    const __half* Bg = B + (size_t)(bn+lrow)*K + lseg*8;
    const uint32_t sOffA0 = (uint32_t)lrow*80 + lseg*16;
    const uint32_t sOffA1 = (uint32_t)(lrow+64)*80 + lseg*16;

    const uint32_t aBase = sb + (uint32_t)((wm*32 + (lane&15))*80 + (lane>>4)*16);
    const uint32_t bBase = sb + 10240u +
        (uint32_t)((wn*64 + (lane&7) + ((lane>>4)&1)*8)*80 + ((lane>>3)&1)*16);

    float acc[2][8][4];
#pragma unroll
    for(int i=0;i<2;i++)
#pragma unroll
        for(int j=0;j<8;j++)
#pragma unroll
            for(int q=0;q<4;q++) acc[i][j][q]=0.f;

    const int nit = K >> 5;

#pragma unroll
    for (int s=0; s<3; s++){
        uint32_t st = sb + (uint32_t)s*GSTAGE_BYTES;
        size_t koff = (size_t)s*32;
        cp16(st + sOffA0,          Ag + koff);
        cp16(st + sOffA1,          Ag + (size_t)64*K + koff);
        cp16(st + 10240 + sOffA0,  Bg + koff);
        cp16(st + 10240 + sOffA1,  Bg + (size_t)64*K + koff);
        CP_COMMIT();
    }

    for (int it=0; it<nit; it++){
        if (it < nit-3)       CP_WAIT(2);
        else if (it == nit-2) CP_WAIT(1);
        else if (it == nit-1) CP_WAIT(0);
        else                  CP_WAIT(2);
        __syncthreads();
        if (it + 3 < nit){
            int ss = (it+3) & 3;
            uint32_t st = sb + (uint32_t)ss*GSTAGE_BYTES;
            size_t koff = (size_t)(it+3)*32;
            cp16(st + sOffA0,          Ag + koff);
            cp16(st + sOffA1,          Ag + (size_t)64*K + koff);
            cp16(st + 10240 + sOffA0,  Bg + koff);
            cp16(st + 10240 + sOffA1,  Bg + (size_t)64*K + koff);
            CP_COMMIT();
        }
        const uint32_t stoff = (uint32_t)(it & 3)*GSTAGE_BYTES;
#pragma unroll
        for (int ks=0; ks<2; ks++){
            unsigned af0[4], af1[4];
            ldsm_x4(af0, aBase + stoff + ks*32);
            ldsm_x4(af1, aBase + stoff + 1280 + ks*32);
#pragma unroll
            for (int jp=0; jp<4; jp++){
                unsigned bf[4];
                ldsm_x4(bf, bBase + stoff + (uint32_t)jp*1280 + ks*32);
                mma_fp16(acc[0][2*jp  ], af0, bf);
                mma_fp16(acc[0][2*jp+1], af0, bf+2);
                mma_fp16(acc[1][2*jp  ], af1, bf);
                mma_fp16(acc[1][2*jp+1], af1, bf+2);
            }
        }
    }

#pragma unroll
    for(int i=0;i<2;i++){
#pragma unroll
        for(int rr=0;rr<2;rr++){
            int row = bm + wm*32 + i*16 + gid + rr*8;
#pragma unroll
            for(int j=0;j<8;j++){
                int col = bn + wn*64 + j*8 + tg*2;
                float v0 = acc[i][j][rr*2+0];
                float v1 = acc[i][j][rr*2+1];
                if (EPI == EP_BIAS) { v0 += bias[col]; v1 += bias[col+1]; }
                else if (EPI == EP_BIAS_RES) {
                    v0 += bias[col]   + res[(size_t)row*N+col];
                    v1 += bias[col+1] + res[(size_t)row*N+col+1];
                }
                else if (EPI == EP_BIAS_GELU) {
                    v0 += bias[col];   v1 += bias[col+1];
                    v0 = 0.5f*v0*(1.f + erff(v0*0.70710678118654752f));
                    v1 = 0.5f*v1*(1.f + erff(v1*0.70710678118654752f));
                }
                else if (EPI == EP_PATCH) {
                    int pb = row / 196, pp = row - pb*196;
                    int tt = pp + 1;
                    v0 = (v0 + bias[col])   + res[(size_t)tt*CDIM + col];
                    v1 = (v1 + bias[col+1]) + res[(size_t)tt*CDIM + col+1];
                    *(float2*)((float*)C + ((size_t)pb*NSEQ + tt)*CDIM + col) = make_float2(v0, v1);
                    continue;
                }
                if (sizeof(OT)==2) {
                    *(__half2*)((__half*)C + (size_t)row*N + col) = __floats2half2_rn(v0, v1);
                } else {
                    *(float2*)((float*)C + (size_t)row*N + col) = make_float2(v0, v1);
                }
            }
        }
    }
}

// ---------------- patch im2col -> fp16 ----------------
__global__ void im2col_patch(const float* __restrict__ x, __half* __restrict__ A)
{
    int i = blockIdx.x*256 + threadIdx.x;
    if (i >= NPAT*CDIM) return;
    int p = i / CDIM, kidx = i - p*CDIM;
    int b = p / 196, pp = p - b*196;
    int py = pp / 14, px = pp - py*14;
    int c = kidx >> 8;
    int rem = kidx & 255;
    int iy = rem >> 4, ix = rem & 15;
    A[i] = __float2half(x[(((size_t)b*3 + c)*224 + (py*16+iy))*224 + (px*16+ix)]);
}

// ---------------- cls/loc token rows ----------------
__global__ void cls_loc_rows(const float* __restrict__ cls, const float* __restrict__ loc,
                             const float* __restrict__ pos, const float* __restrict__ loce,
                             float* __restrict__ T)
{
    int i = blockIdx.x*256 + threadIdx.x;
    if (i >= NB*2*CDIM) return;
    int b = i / (2*CDIM), r = i - b*2*CDIM;
    int which = r / CDIM, c = r - which*CDIM;
    float v;
    int tt;
    if (which == 0){ tt = 0;   v = cls[c] + pos[c]; }
    else           { tt = 197; v = loc[c] + loce[c]; }
    T[((size_t)b*NSEQ + tt)*CDIM + c] = v;
}

// ---------------- layernorm: warp per row ----------------
__launch_bounds__(256)
__global__ void ln_kernel(const float* __restrict__ X, const float* __restrict__ w,
                          const float* __restrict__ bb, __half* __restrict__ Y)
{
    int row = blockIdx.x*8 + (threadIdx.x>>5);
    int lane = threadIdx.x & 31;
    const float4* x4 = (const float4*)(X + (size_t)row*CDIM);
    float4 v[6];
    float s = 0.f;
#pragma unroll
    for (int i=0;i<6;i++){
        v[i] = x4[lane + 32*i];
        s += v[i].x + v[i].y + v[i].z + v[i].w;
    }
#pragma unroll
    for (int o=16;o;o>>=1) s += __shfl_xor_sync(0xffffffffu, s, o);
    float m = s * (1.f/768.f);
    float q = 0.f;
#pragma unroll
    for (int i=0;i<6;i++){
        float d0=v[i].x-m, d1=v[i].y-m, d2=v[i].z-m, d3=v[i].w-m;
        q += d0*d0 + d1*d1 + d2*d2 + d3*d3;
    }
#pragma unroll
    for (int o=16;o;o>>=1) q += __shfl_xor_sync(0xffffffffu, q, o);
    float rs = rsqrtf(q*(1.f/768.f) + 1e-5f);
    __half* y = Y + (size_t)row*CDIM;
#pragma unroll
    for (int i=0;i<6;i++){
        int col = (lane + 32*i)*4;
        float4 wv = *(const float4*)(w + col);
        float4 bv = *(const float4*)(bb + col);
        __half2 h0 = __floats2half2_rn((v[i].x-m)*rs*wv.x + bv.x, (v[i].y-m)*rs*wv.y + bv.y);
        __half2 h1 = __floats2half2_rn((v[i].z-m)*rs*wv.z + bv.z, (v[i].w-m)*rs*wv.w + bv.w);
        *(__half2*)(y + col)     = h0;
        *(__half2*)(y + col + 2) = h1;
    }
}

// ---------------- mask precompute ----------------
__launch_bounds__(256)
__global__ void mask_pre(const __half* __restrict__ qkv, float* __restrict__ mask)
{
    int b = blockIdx.x;
    __shared__ float q197[CDIM];
    int tid = threadIdx.x;
    const __half* qrow = qkv + ((size_t)b*NSEQ + 197)*(3*CDIM);
    for (int i=tid;i<CDIM;i+=256) q197[i]=__half2float(qrow[i]);
    __syncthreads();
    int warp=tid>>5, lane=tid&31;
    for (int k=warp; k<NSEQ; k+=8){
        const __half* krow = qkv + ((size_t)b*NSEQ + k)*(3*CDIM) + CDIM;
        float s=0.f;
        for (int d=lane; d<CDIM; d+=32) s = fmaf(q197[d], __half2float(krow[d]), s);
#pragma unroll
        for (int o=16;o;o>>=1) s += __shfl_xor_sync(0xffffffffu, s, o);
        if (lane==0) mask[(size_t)b*NSEQ + k] = 1.f/(1.f + __expf(-s*(0.125f/12.f)));
    }
}

// ---------------- flash attention per (b,h): mask folded into V ----------------
// softmax(S)*diag(m)*V == softmax(S)*(diag(m)*V): scale V rows by m[k] at load.
// smem: Ks [208][72] fp16 | Vs [64][216] fp16 = 57600 B -> 3 CTAs/SM
#define ATT_SMEM (29952 + 27648)   // 57600
template<int USE_MASK>
__global__ void __launch_bounds__(256,3) attn_flash(
    const __half* __restrict__ qkv, const float* __restrict__ mask,
    __half* __restrict__ O)
{
    int bh = blockIdx.x;
    int b = bh / NHEAD, h = bh - b*NHEAD;
    extern __shared__ char smem[];
    __half* Ks = (__half*)smem;                   // [208][72]
    __half* Vs = (__half*)(smem + 29952);         // [64][216]
    const int tid=threadIdx.x, warp=tid>>5, lane=tid&31;
    const int gid=lane>>2, tg=lane&3;
    const __half* base = qkv + (size_t)b*NSEQ*(3*CDIM) + h*HD;
    const uint4 z4 = make_uint4(0,0,0,0);

    // K: 16B vector loads into padded smem
    for (int i = tid; i < 208*8; i += 256){
        int t = i>>3, seg = i&7;
        uint4 kv = z4;
        if (t < NSEQ)
            kv = *(const uint4*)(base + (size_t)t*(3*CDIM) + CDIM + seg*8);
        *(uint4*)&Ks[t*72 + seg*8] = kv;
    }
    // V: 16B vector loads + transpose; mask folded into V rows when USE_MASK
    for (int i = tid; i < 208*8; i += 256){
        int k = i>>3, seg = i&7;
        uint4 vv = z4;
        if (k < NSEQ) vv = *(const uint4*)(base + (size_t)k*(3*CDIM) + 2*CDIM + seg*8);
        __half tmp[8];
        *(uint4*)tmp = vv;
        if (USE_MASK){
            float mk = (k < NSEQ) ? mask[(size_t)b*NSEQ + k] : 0.f;
#pragma unroll
            for (int j=0;j<8;j++)
                Vs[(seg*8+j)*216 + k] = __float2half(__half2float(tmp[j]) * mk);
        } else {
#pragma unroll
            for (int j=0;j<8;j++) Vs[(seg*8+j)*216 + k] = tmp[j];
        }
    }
    __syncthreads();

    __half* Oh = O + (size_t)b*NSEQ*CDIM + h*HD;
    for (int mt = warp; mt < 13; mt += 8){
        int m0 = mt*16;
        const bool qv0 = (m0 + gid)     < NSEQ;
        const bool qv1 = (m0 + gid + 8) < NSEQ;
        const __half* q0p = base + (size_t)(m0+gid)*(3*CDIM);
        const __half* q1p = base + (size_t)(m0+gid+8)*(3*CDIM);
        unsigned af[4][4];
#pragma unroll
        for (int ks=0; ks<4; ks++){
            int kb = ks*16 + 2*tg;
            af[ks][0] = qv0 ? *(const unsigned*)(q0p + kb)     : 0u;
            af[ks][1] = qv1 ? *(const unsigned*)(q1p + kb)     : 0u;
            af[ks][2] = qv0 ? *(const unsigned*)(q0p + kb + 8) : 0u;
            af[ks][3] = qv1 ? *(const unsigned*)(q1p + kb + 8) : 0u;
        }
        float accO[8][4];
#pragma unroll
        for (int nt=0;nt<8;nt++)
#pragma unroll
            for (int q2=0;q2<4;q2++) accO[nt][q2]=0.f;
        float m0r = -1e30f, m1r = -1e30f, l0r = 0.f, l1r = 0.f;

        for (int kt = 0; kt < 13; kt++){
            int n0 = kt*16;
            float s[2][4];
#pragma unroll
            for (int t2=0; t2<2; t2++){
                float a4[4] = {0.f,0.f,0.f,0.f};
#pragma unroll
                for (int ks=0; ks<4; ks++){
                    int kb = ks*16 + 2*tg;
                    unsigned bb[2];
                    bb[0] = *(const unsigned*)&Ks[(n0+t2*8+gid)*72 + kb  ];
                    bb[1] = *(const unsigned*)&Ks[(n0+t2*8+gid)*72 + kb+8];
                    mma_fp16(a4, af[ks], bb);
                }
                int c0 = n0 + t2*8 + 2*tg;
                s[t2][0] = (c0   < NSEQ) ? a4[0]*0.125f : -1e30f;
                s[t2][1] = (c0+1 < NSEQ) ? a4[1]*0.125f : -1e30f;
                s[t2][2] = (c0   < NSEQ) ? a4[2]*0.125f : -1e30f;
                s[t2][3] = (c0+1 < NSEQ) ? a4[3]*0.125f : -1e30f;
            }
            float tm0 = fmaxf(fmaxf(s[0][0], s[0][1]), fmaxf(s[1][0], s[1][1]));
            float tm1 = fmaxf(fmaxf(s[0][2], s[0][3]), fmaxf(s[1][2], s[1][3]));
            tm0 = fmaxf(tm0, __shfl_xor_sync(0xffffffffu, tm0, 1));
            tm0 = fmaxf(tm0, __shfl_xor_sync(0xffffffffu, tm0, 2));
            tm1 = fmaxf(tm1, __shfl_xor_sync(0xffffffffu, tm1, 1));
            tm1 = fmaxf(tm1, __shfl_xor_sync(0xffffffffu, tm1, 2));
            float mn0 = fmaxf(m0r, tm0), mn1 = fmaxf(m1r, tm1);
            float sc0 = __expf(m0r - mn0), sc1 = __expf(m1r - mn1);
            float p[2][4];
#pragma unroll
            for (int t2=0; t2<2; t2++){
                p[t2][0] = __expf(s[t2][0] - mn0);
                p[t2][1] = __expf(s[t2][1] - mn0);
                p[t2][2] = __expf(s[t2][2] - mn1);
                p[t2][3] = __expf(s[t2][3] - mn1);
            }
            float ls0 = p[0][0]+p[0][1]+p[1][0]+p[1][1];
            float ls1 = p[0][2]+p[0][3]+p[1][2]+p[1][3];
            ls0 += __shfl_xor_sync(0xffffffffu, ls0, 1);
            ls0 += __shfl_xor_sync(0xffffffffu, ls0, 2);
            ls1 += __shfl_xor_sync(0xffffffffu, ls1, 1);
            ls1 += __shfl_xor_sync(0xffffffffu, ls1, 2);
            l0r = l0r*sc0 + ls0;
            l1r = l1r*sc1 + ls1;
            m0r = mn0; m1r = mn1;
#pragma unroll
            for (int nt=0; nt<8; nt++){
                accO[nt][0]*=sc0; accO[nt][1]*=sc0;
                accO[nt][2]*=sc1; accO[nt][3]*=sc1;
            }
            unsigned ap[4];
            {
                __half2 h0 = __floats2half2_rn(p[0][0], p[0][1]);
                __half2 h1 = __floats2half2_rn(p[0][2], p[0][3]);
                __half2 h2 = __floats2half2_rn(p[1][0], p[1][1]);
                __half2 h3 = __floats2half2_rn(p[1][2], p[1][3]);
                ap[0]=*(unsigned*)&h0; ap[1]=*(unsigned*)&h1;
                ap[2]=*(unsigned*)&h2; ap[3]=*(unsigned*)&h3;
            }
            int kv = n0 + 2*tg;
#pragma unroll
            for (int nt=0; nt<8; nt++){
                unsigned bb[2];
                bb[0] = *(const unsigned*)&Vs[(nt*8+gid)*216 + kv  ];
                bb[1] = *(const unsigned*)&Vs[(nt*8+gid)*216 + kv+8];
                mma_fp16(accO[nt], ap, bb);
            }
        }
        float inv0 = 1.f/l0r, inv1 = 1.f/l1r;
        int q0 = m0 + gid, q1 = m0 + gid + 8;
        if (q0 < NSEQ){
#pragma unroll
            for (int nt=0; nt<8; nt++)
                *(__half2*)&Oh[(size_t)q0*CDIM + nt*8 + tg*2] =
                    __floats2half2_rn(accO[nt][0]*inv0, accO[nt][1]*inv0);
        }
        if (q1 < NSEQ){
#pragma unroll
            for (int nt=0; nt<8; nt++)
                *(__half2*)&Oh[(size_t)q1*CDIM + nt*8 + tg*2] =
                    __floats2half2_rn(accO[nt][2]*inv1, accO[nt][3]*inv1);
        }
    }
}

// ---------------- head features ----------------
__launch_bounds__(256)
__global__ void sfeat_kernel(const __half* __restrict__ T, float* __restrict__ SF)
{
    int i = blockIdx.x*256 + threadIdx.x;
    if (i >= NB*CDIM) return;
    int b = i / CDIM, c = i - b*CDIM;
    const __half* base = T + ((size_t)b*NSEQ + 1)*CDIM + c;
    float tot=0.f, r0=0.f, r13=0.f, c0s=0.f, c13s=0.f;
    for (int u=0; u<14; u++) {
        for (int v=0; v<14; v++) {
            float val = __half2float(base[(size_t)(u*14+v)*CDIM]);
            tot += val;
            if (u==0)  r0  += val;
            if (u==13) r13 += val;
            if (v==0)  c0s += val;
            if (v==13) c13s += val;
        }
    }
    float x00 = __half2float(base[0]);
    float x0e = __half2float(base[(size_t)13*CDIM]);
    float xe0 = __half2float(base[(size_t)(13*14)*CDIM]);
    float xee = __half2float(base[(size_t)(13*14+13)*CDIM]);
    float* o = SF + (size_t)b*6912 + c*9;
    for (int dy=0; dy<3; dy++)
        for (int dx=0; dx<3; dx++) {
            float s = tot;
            if (dy==0) s -= r13;
            if (dy==2) s -= r0;
            if (dx==0) s -= c13s;
            if (dx==2) s -= c0s;
            if (dy==0 && dx==0) s += xee;
            if (dy==0 && dx==2) s += xe0;
            if (dy==2 && dx==0) s += x0e;
            if (dy==2 && dx==2) s += x00;
            o[dy*3+dx] = s;
        }
}

// ---------------- logits ----------------
__launch_bounds__(256)
__global__ void head_kernel(const float* __restrict__ SF, const float* __restrict__ W,
                            const float* __restrict__ bias, float* __restrict__ out)
{
    int gw = (blockIdx.x*256 + threadIdx.x) >> 5;
    int lane = threadIdx.x & 31;
    if (gw >= NB*200) return;
    int b = gw / 200, cls = gw - b*200;
    const float* a = SF + (size_t)b*6912;
    const float* w = W + (size_t)cls*6912;
    float s = 0.f;
    for (int k = lane; k < 6912; k += 32) s = fmaf(a[k], w[k], s);
#pragma unroll
    for (int o=16;o;o>>=1) s += __shfl_xor_sync(0xffffffffu, s, o);
    if (lane==0) out[gw] = s*(1.f/196.f) + bias[cls];
}

// ---------------- final mask outputs ----------------
__launch_bounds__(256)
__global__ void final_mask(const float* __restrict__ Mlayers, const float* __restrict__ gk,
                           float* __restrict__ out)
{
    int b = blockIdx.x;
    __shared__ float ma[196];
    __shared__ float red[8];
    int tid = threadIdx.x;
    if (tid < 196) {
        float s = 0.f;
        for (int l=9; l<12; l++) s += Mlayers[((size_t)l*NB + b)*NSEQ + 1 + tid];
        ma[tid] = s * (1.f/3.f);
    }
    __syncthreads();
    float part = (tid < 196) ? ma[tid] : 0.f;
#pragma unroll
    for (int o=16;o;o>>=1) part += __shfl_xor_sync(0xffffffffu, part, o);
    if ((tid&31)==0) red[tid>>5] = part;
    __syncthreads();
    if (tid==0){ float t=0.f; for(int i=0;i<8;i++) t+=red[i]; out[12800 + b] = t*(1.f/196.f); }
    float t3 = 0.f;
    if (tid < 196) {
        int y = tid/14, x = tid - y*14;
        float m = 0.f;
        for (int dy=0; dy<3; dy++)
            for (int dx=0; dx<3; dx++) {
                int yy = y+dy-1, xx = x+dx-1;
                if (yy>=0 && yy<14 && xx>=0 && xx<14)
                    m += gk[dy*3+dx]*ma[yy*14+xx];
            }
        t3 = (1.f - m)*m;
    }
    __syncthreads();
#pragma unroll
    for (int o=16;o;o>>=1) t3 += __shfl_xor_sync(0xffffffffu, t3, o);
    if ((tid&31)==0) red[tid>>5] = t3;
    __syncthreads();
    if (tid==0){ float t=0.f; for(int i=0;i<8;i++) t+=red[i]; out[12864 + b] = t*(1.f/196.f); }
}

// ---------------- launch ----------------
extern "C" void kernel_launch(void* const* d_in, const int* in_sizes, int n_in,
                              void* d_out, int out_size)
{
    const float* x       = (const float*)d_in[0];
    const float* patch_w = (const float*)d_in[1];
    const float* patch_b = (const float*)d_in[2];
    const float* cls_tok = (const float*)d_in[3];
    const float* loc_tok = (const float*)d_in[4];
    const float* pos_emb = (const float*)d_in[5];
    const float* loc_emb = (const float*)d_in[6];
    const float* ln1_w   = (const float*)d_in[7];
    const float* ln1_b   = (const float*)d_in[8];
    const float* qkv_w   = (const float*)d_in[9];
    const float* proj_w  = (const float*)d_in[10];
    const float* proj_b  = (const float*)d_in[11];
    const float* ln2_w   = (const float*)d_in[12];
    const float* ln2_b   = (const float*)d_in[13];
    const float* fc1_w   = (const float*)d_in[14];
    const float* fc1_b   = (const float*)d_in[15];
    const float* fc2_w   = (const float*)d_in[16];
    const float* fc2_b   = (const float*)d_in[17];
    const float* norm_w  = (const float*)d_in[18];
    const float* norm_b  = (const float*)d_in[19];
    const float* head_w  = (const float*)d_in[20];
    const float* head_b  = (const float*)d_in[21];
    const float* gk      = (const float*)d_in[22];
    float* out = (float*)d_out;

    float *t, *maskb, *sfeat;
    __half *ah, *qkvh, *oh, *hh, *wh;
    cudaGetSymbolAddress((void**)&t,     g_t);
    cudaGetSymbolAddress((void**)&maskb, g_mask);
    cudaGetSymbolAddress((void**)&sfeat, g_sfeat);
    cudaGetSymbolAddress((void**)&ah,    g_ah);
    cudaGetSymbolAddress((void**)&qkvh,  g_qkvh);
    cudaGetSymbolAddress((void**)&oh,    g_oh);
    cudaGetSymbolAddress((void**)&hh,    g_hh);
    cudaGetSymbolAddress((void**)&wh,    g_wh);

    cudaFuncSetAttribute(attn_flash<0>, cudaFuncAttributeMaxDynamicSharedMemorySize, ATT_SMEM);
    cudaFuncSetAttribute(attn_flash<1>, cudaFuncAttributeMaxDynamicSharedMemorySize, ATT_SMEM);
    cudaFuncSetAttribute(gemm_h2<EP_PATCH,float>,      cudaFuncAttributeMaxDynamicSharedMemorySize, G_SMEM);
    cudaFuncSetAttribute(gemm_h2<EP_NONE,__half>,      cudaFuncAttributeMaxDynamicSharedMemorySize, G_SMEM);
    cudaFuncSetAttribute(gemm_h2<EP_BIAS_RES,float>,   cudaFuncAttributeMaxDynamicSharedMemorySize, G_SMEM);
    cudaFuncSetAttribute(gemm_h2<EP_BIAS_GELU,__half>, cudaFuncAttributeMaxDynamicSharedMemorySize, G_SMEM);

    f2h_all<<<(R_FC2+255)/256, 256>>>(patch_w, qkv_w, proj_w, fc1_w, fc2_w, wh);

    im2col_patch<<<(NPAT*CDIM+255)/256, 256>>>(x, ah);
    cls_loc_rows<<<(NB*2*CDIM+255)/256, 256>>>(cls_tok, loc_tok, pos_emb, loc_emb, t);
    gemm_h2<EP_PATCH,float><<<dim3(6,98), 256, G_SMEM>>>(ah, wh + W_PATCH, patch_b, pos_emb,
                                                         t, NPAT, CDIM, CDIM);

    for (int d=0; d<12; d++) {
        ln_kernel<<<NTOK/8, 256>>>(t, ln1_w + d*CDIM, ln1_b + d*CDIM, ah);
        gemm_h2<EP_NONE,__half><<<dim3(18,99), 256, G_SMEM>>>(ah, wh + W_QKV + (size_t)d*3*CDIM*CDIM,
                                                              nullptr, nullptr, qkvh, NTOK, 3*CDIM, CDIM);
        if (d >= 9){
            mask_pre<<<NB, 256>>>(qkvh, maskb + (size_t)d*NB*NSEQ);
            attn_flash<1><<<NB*NHEAD, 256, ATT_SMEM>>>(qkvh, maskb + (size_t)d*NB*NSEQ, oh);
        } else {
            attn_flash<0><<<NB*NHEAD, 256, ATT_SMEM>>>(qkvh, nullptr, oh);
        }
        gemm_h2<EP_BIAS_RES,float><<<dim3(6,99), 256, G_SMEM>>>(oh, wh + W_PROJ + (size_t)d*CDIM*CDIM,
                                                                proj_b + d*CDIM, t, t, NTOK, CDIM, CDIM);
        ln_kernel<<<NTOK/8, 256>>>(t, ln2_w + d*CDIM, ln2_b + d*CDIM, ah);
        gemm_h2<EP_BIAS_GELU,__half><<<dim3(24,99), 256, G_SMEM>>>(ah, wh + W_FC1 + (size_t)d*4*CDIM*CDIM,
                                                                   fc1_b + d*4*CDIM, nullptr, hh, NTOK, 4*CDIM, CDIM);
        gemm_h2<EP_BIAS_RES,float><<<dim3(6,99), 256, G_SMEM>>>(hh, wh + W_FC2 + (size_t)d*CDIM*4*CDIM,
                                                                fc2_b + d*CDIM, t, t, NTOK, CDIM, 4*CDIM);
    }

    ln_kernel<<<NTOK/8, 256>>>(t, norm_w, norm_b, ah);
    sfeat_kernel<<<(NB*CDIM+255)/256, 256>>>(ah, sfeat);
    head_kernel<<<(NB*200*32+255)/256, 256>>>(sfeat, head_w, head_b, out);
    final_mask<<<NB, 256>>>(maskb, gk, out);
}

// round 17
// speedup vs baseline: 1.0060x; 1.0060x over previous
#include <cuda_runtime.h>
#include <cuda_fp16.h>
#include <math.h>
#include <stdint.h>

// ---------------- problem constants ----------------
#define NB    64
#define NSEQ  198
#define NTOK  (NB*NSEQ)      // 12672
#define NPAT  (NB*196)       // 12544
#define CDIM  768
#define NHEAD 12
#define HD    64

// weight fp16 pool offsets (elements)
#define W_PATCH 0
#define W_QKV   589824
#define W_PROJ  21823488
#define W_FC1   28901376
#define W_FC2   57212928
#define W_TOTAL 85524480

// ---------------- scratch ----------------
__device__ float  g_t   [(size_t)NTOK*CDIM];
__device__ float  g_mask[(size_t)12*NB*NSEQ];
__device__ float  g_sfeat[(size_t)NB*6912];
__device__ __half g_ah  [(size_t)NTOK*CDIM];
__device__ __half g_qkvh[(size_t)NTOK*3*CDIM];
__device__ __half g_oh  [(size_t)NTOK*CDIM];
__device__ __half g_hh  [(size_t)NTOK*4*CDIM];
__device__ __half g_wh  [(size_t)W_TOTAL];

enum { EP_NONE=0, EP_BIAS=1, EP_BIAS_RES=2, EP_BIAS_GELU=3, EP_PATCH=4 };

// ---------------- helpers ----------------
__device__ __forceinline__ uint32_t smem_u32(const void* p){
    uint32_t a;
    asm("{ .reg .u64 t; cvta.to.shared.u64 t, %1; cvt.u32.u64 %0, t; }" : "=r"(a) : "l"(p));
    return a;
}
__device__ __forceinline__ void mma_fp16(float c[4], const unsigned a[4], const unsigned b[2]){
    asm volatile("mma.sync.aligned.m16n8k16.row.col.f32.f16.f16.f32 "
        "{%0,%1,%2,%3}, {%4,%5,%6,%7}, {%8,%9}, {%0,%1,%2,%3};\n"
        : "+f"(c[0]),"+f"(c[1]),"+f"(c[2]),"+f"(c[3])
        : "r"(a[0]),"r"(a[1]),"r"(a[2]),"r"(a[3]), "r"(b[0]),"r"(b[1]));
}
__device__ __forceinline__ void ldsm_x4(unsigned r[4], uint32_t a){
    asm volatile("ldmatrix.sync.aligned.m8n8.x4.shared.b16 {%0,%1,%2,%3}, [%4];"
        : "=r"(r[0]),"=r"(r[1]),"=r"(r[2]),"=r"(r[3]) : "r"(a));
}
__device__ __forceinline__ void cp16(uint32_t s, const void* g){
    asm volatile("cp.async.cg.shared.global [%0], [%1], 16;" :: "r"(s), "l"(g));
}
#define CP_COMMIT() asm volatile("cp.async.commit_group;" ::: "memory")
#define CP_WAIT(n)  asm volatile("cp.async.wait_group %0;" :: "n"(n) : "memory")

// ---------------- merged f32 -> f16 convert (all 5 weight tensors, 1 launch) ----------------
// ranges in float4 units
#define R_PATCH 147456
#define R_QKV   (R_PATCH + 5308416)   // 5455872
#define R_PROJ  (R_QKV + 1769472)     // 7225344
#define R_FC1   (R_PROJ + 7077888)    // 14303232
#define R_FC2   (R_FC1 + 7077888)     // 21381120
__global__ void f2h_all(const float* __restrict__ pw, const float* __restrict__ qw,
                        const float* __restrict__ prw, const float* __restrict__ f1w,
                        const float* __restrict__ f2w, __half* __restrict__ dst)
{
    int i = blockIdx.x*256 + threadIdx.x;
    if (i >= R_FC2) return;
    const float* src;
    int off;
    if (i < R_PATCH)      { src = pw;  off = i; }
    else if (i < R_QKV)   { src = qw;  off = i - R_PATCH; }
    else if (i < R_PROJ)  { src = prw; off = i - R_QKV; }
    else if (i < R_FC1)   { src = f1w; off = i - R_PROJ; }
    else                  { src = f2w; off = i - R_FC1; }
    float4 v = ((const float4*)src)[off];
    ((__half2*)dst)[(size_t)i*2  ] = __floats2half2_rn(v.x, v.y);
    ((__half2*)dst)[(size_t)i*2+1] = __floats2half2_rn(v.z, v.w);
}

// ---------------- pipelined fp16 GEMM-NT: C[M,N] = A[M,K]*B[N,K]^T ----------------
#define GSTAGES      4
#define GSTAGE_BYTES 20480
#define G_SMEM       (GSTAGES*GSTAGE_BYTES)   // 81920
template<int EPI, typename OT>
__global__ void __launch_bounds__(256,2) gemm_h2(
    const __half* __restrict__ A, const __half* __restrict__ B,
    const float* __restrict__ bias, const float* __restrict__ res,
    OT* __restrict__ C, int M, int N, int K)
{
    extern __shared__ char smem[];
    const uint32_t sb = smem_u32(smem);
    const int tid=threadIdx.x, warp=tid>>5, lane=tid&31;
    const int wm=warp>>1, wn=warp&1;
    const int gid=lane>>2, tg=lane&3;
    const int bm=blockIdx.y*128, bn=blockIdx.x*128;

    const int lrow = tid>>2, lseg = tid&3;
    const __half* Ag = A + (size_t)(bm+lrow)*K + lseg*8;
    const __half* Bg = B + (size_t)(bn+lrow)*K + lseg*8;
    const uint32_t sOffA0 = (uint32_t)lrow*80 + lseg*16;
    const uint32_t sOffA1 = (uint32_t)(lrow+64)*80 + lseg*16;

    const uint32_t aBase = sb + (uint32_t)((wm*32 + (lane&15))*80 + (lane>>4)*16);
    const uint32_t bBase = sb + 10240u +
        (uint32_t)((wn*64 + (lane&7) + ((lane>>4)&1)*8)*80 + ((lane>>3)&1)*16);

    float acc[2][8][4];
#pragma unroll
    for(int i=0;i<2;i++)
#pragma unroll
        for(int j=0;j<8;j++)
#pragma unroll
            for(int q=0;q<4;q++) acc[i][j][q]=0.f;

    const int nit = K >> 5;

#pragma unroll
    for (int s=0; s<3; s++){
        uint32_t st = sb + (uint32_t)s*GSTAGE_BYTES;
        size_t koff = (size_t)s*32;
        cp16(st + sOffA0,          Ag + koff);
        cp16(st + sOffA1,          Ag + (size_t)64*K + koff);
        cp16(st + 10240 + sOffA0,  Bg + koff);
        cp16(st + 10240 + sOffA1,  Bg + (size_t)64*K + koff);
        CP_COMMIT();
    }

    for (int it=0; it<nit; it++){
        if (it < nit-3)       CP_WAIT(2);
        else if (it == nit-2) CP_WAIT(1);
        else if (it == nit-1) CP_WAIT(0);
        else                  CP_WAIT(2);
        __syncthreads();
        if (it + 3 < nit){
            int ss = (it+3) & 3;
            uint32_t st = sb + (uint32_t)ss*GSTAGE_BYTES;
            size_t koff = (size_t)(it+3)*32;
            cp16(st + sOffA0,          Ag + koff);
            cp16(st + sOffA1,          Ag + (size_t)64*K + koff);
            cp16(st + 10240 + sOffA0,  Bg + koff);
            cp16(st + 10240 + sOffA1,  Bg + (size_t)64*K + koff);
            CP_COMMIT();
        }
        const uint32_t stoff = (uint32_t)(it & 3)*GSTAGE_BYTES;
#pragma unroll
        for (int ks=0; ks<2; ks++){
            unsigned af0[4], af1[4];
            ldsm_x4(af0, aBase + stoff + ks*32);
            ldsm_x4(af1, aBase + stoff + 1280 + ks*32);
#pragma unroll
            for (int jp=0; jp<4; jp++){
                unsigned bf[4];
                ldsm_x4(bf, bBase + stoff + (uint32_t)jp*1280 + ks*32);
                mma_fp16(acc[0][2*jp  ], af0, bf);
                mma_fp16(acc[0][2*jp+1], af0, bf+2);
                mma_fp16(acc[1][2*jp  ], af1, bf);
                mma_fp16(acc[1][2*jp+1], af1, bf+2);
            }
        }
    }

#pragma unroll
    for(int i=0;i<2;i++){
#pragma unroll
        for(int rr=0;rr<2;rr++){
            int row = bm + wm*32 + i*16 + gid + rr*8;
#pragma unroll
            for(int j=0;j<8;j++){
                int col = bn + wn*64 + j*8 + tg*2;
                float v0 = acc[i][j][rr*2+0];
                float v1 = acc[i][j][rr*2+1];
                if (EPI == EP_BIAS) { v0 += bias[col]; v1 += bias[col+1]; }
                else if (EPI == EP_BIAS_RES) {
                    v0 += bias[col]   + res[(size_t)row*N+col];
                    v1 += bias[col+1] + res[(size_t)row*N+col+1];
                }
                else if (EPI == EP_BIAS_GELU) {
                    v0 += bias[col];   v1 += bias[col+1];
                    v0 = 0.5f*v0*(1.f + erff(v0*0.70710678118654752f));
                    v1 = 0.5f*v1*(1.f + erff(v1*0.70710678118654752f));
                }
                else if (EPI == EP_PATCH) {
                    int pb = row / 196, pp = row - pb*196;
                    int tt = pp + 1;
                    v0 = (v0 + bias[col])   + res[(size_t)tt*CDIM + col];
                    v1 = (v1 + bias[col+1]) + res[(size_t)tt*CDIM + col+1];
                    *(float2*)((float*)C + ((size_t)pb*NSEQ + tt)*CDIM + col) = make_float2(v0, v1);
                    continue;
                }
                if (sizeof(OT)==2) {
                    *(__half2*)((__half*)C + (size_t)row*N + col) = __floats2half2_rn(v0, v1);
                } else {
                    *(float2*)((float*)C + (size_t)row*N + col) = make_float2(v0, v1);
                }
            }
        }
    }
}

// ---------------- patch im2col -> fp16 ----------------
__global__ void im2col_patch(const float* __restrict__ x, __half* __restrict__ A)
{
    int i = blockIdx.x*256 + threadIdx.x;
    if (i >= NPAT*CDIM) return;
    int p = i / CDIM, kidx = i - p*CDIM;
    int b = p / 196, pp = p - b*196;
    int py = pp / 14, px = pp - py*14;
    int c = kidx >> 8;
    int rem = kidx & 255;
    int iy = rem >> 4, ix = rem & 15;
    A[i] = __float2half(x[(((size_t)b*3 + c)*224 + (py*16+iy))*224 + (px*16+ix)]);
}

// ---------------- cls/loc token rows (tokens 0 and 197 per batch) ----------------
__global__ void cls_loc_rows(const float* __restrict__ cls, const float* __restrict__ loc,
                             const float* __restrict__ pos, const float* __restrict__ loce,
                             float* __restrict__ T)
{
    int i = blockIdx.x*256 + threadIdx.x;
    if (i >= NB*2*CDIM) return;
    int b = i / (2*CDIM), r = i - b*2*CDIM;
    int which = r / CDIM, c = r - which*CDIM;
    float v;
    int tt;
    if (which == 0){ tt = 0;   v = cls[c] + pos[c]; }
    else           { tt = 197; v = loc[c] + loce[c]; }
    T[((size_t)b*NSEQ + tt)*CDIM + c] = v;
}

// ---------------- layernorm: warp per row, fp32 in, fp16 out ----------------
__launch_bounds__(256)
__global__ void ln_kernel(const float* __restrict__ X, const float* __restrict__ w,
                          const float* __restrict__ bb, __half* __restrict__ Y)
{
    int row = blockIdx.x*8 + (threadIdx.x>>5);
    int lane = threadIdx.x & 31;
    const float4* x4 = (const float4*)(X + (size_t)row*CDIM);
    float4 v[6];
    float s = 0.f;
#pragma unroll
    for (int i=0;i<6;i++){
        v[i] = x4[lane + 32*i];
        s += v[i].x + v[i].y + v[i].z + v[i].w;
    }
#pragma unroll
    for (int o=16;o;o>>=1) s += __shfl_xor_sync(0xffffffffu, s, o);
    float m = s * (1.f/768.f);
    float q = 0.f;
#pragma unroll
    for (int i=0;i<6;i++){
        float d0=v[i].x-m, d1=v[i].y-m, d2=v[i].z-m, d3=v[i].w-m;
        q += d0*d0 + d1*d1 + d2*d2 + d3*d3;
    }
#pragma unroll
    for (int o=16;o;o>>=1) q += __shfl_xor_sync(0xffffffffu, q, o);
    float rs = rsqrtf(q*(1.f/768.f) + 1e-5f);
    __half* y = Y + (size_t)row*CDIM;
#pragma unroll
    for (int i=0;i<6;i++){
        int col = (lane + 32*i)*4;
        float4 wv = *(const float4*)(w + col);
        float4 bv = *(const float4*)(bb + col);
        __half2 h0 = __floats2half2_rn((v[i].x-m)*rs*wv.x + bv.x, (v[i].y-m)*rs*wv.y + bv.y);
        __half2 h1 = __floats2half2_rn((v[i].z-m)*rs*wv.z + bv.z, (v[i].w-m)*rs*wv.w + bv.w);
        *(__half2*)(y + col)     = h0;
        *(__half2*)(y + col + 2) = h1;
    }
}

// ---------------- mask precompute (fp16 qkv) ----------------
__launch_bounds__(256)
__global__ void mask_pre(const __half* __restrict__ qkv, float* __restrict__ mask)
{
    int b = blockIdx.x;
    __shared__ float q197[CDIM];
    int tid = threadIdx.x;
    const __half* qrow = qkv + ((size_t)b*NSEQ + 197)*(3*CDIM);
    for (int i=tid;i<CDIM;i+=256) q197[i]=__half2float(qrow[i]);
    __syncthreads();
    int warp=tid>>5, lane=tid&31;
    for (int k=warp; k<NSEQ; k+=8){
        const __half* krow = qkv + ((size_t)b*NSEQ + k)*(3*CDIM) + CDIM;
        float s=0.f;
        for (int d=lane; d<CDIM; d+=32) s = fmaf(q197[d], __half2float(krow[d]), s);
#pragma unroll
        for (int o=16;o;o>>=1) s += __shfl_xor_sync(0xffffffffu, s, o);
        if (lane==0) mask[(size_t)b*NSEQ + k] = 1.f/(1.f + __expf(-s*(0.125f/12.f)));
    }
}

// ---------------- flash attention per (b,h): online softmax, vectorized loads ----------------
#define ATT_SMEM (29952 + 29952 + 27648 + 832)   // 88384
template<int USE_MASK>
__global__ void __launch_bounds__(256,2) attn_flash(
    const __half* __restrict__ qkv, const float* __restrict__ mask,
    __half* __restrict__ O)
{
    int bh = blockIdx.x;
    int b = bh / NHEAD, h = bh - b*NHEAD;
    extern __shared__ char smem[];
    __half* Qs = (__half*)smem;                   // [208][72]
    __half* Ks = (__half*)(smem + 29952);         // [208][72]
    __half* Vs = (__half*)(smem + 59904);         // [64][216]
    float*  msk = (float*)(smem + 87552);         // [208]
    const int tid=threadIdx.x, warp=tid>>5, lane=tid&31;
    const int gid=lane>>2, tg=lane&3;
    const __half* base = qkv + (size_t)b*NSEQ*(3*CDIM) + h*HD;
    const uint4 z4 = make_uint4(0,0,0,0);

    for (int i = tid; i < 208*8; i += 256){
        int t = i>>3, seg = i&7;
        uint4 qv = z4, kv = z4;
        if (t < NSEQ){
            qv = *(const uint4*)(base + (size_t)t*(3*CDIM) + seg*8);
            kv = *(const uint4*)(base + (size_t)t*(3*CDIM) + CDIM + seg*8);
        }
        *(uint4*)&Qs[t*72 + seg*8] = qv;
        *(uint4*)&Ks[t*72 + seg*8] = kv;
    }
    for (int i = tid; i < 208*8; i += 256){
        int k = i>>3, seg = i&7;
        uint4 vv = z4;
        if (k < NSEQ) vv = *(const uint4*)(base + (size_t)k*(3*CDIM) + 2*CDIM + seg*8);
        __half tmp[8];
        *(uint4*)tmp = vv;
#pragma unroll
        for (int j=0;j<8;j++) Vs[(seg*8+j)*216 + k] = tmp[j];
    }
    if (USE_MASK && tid < 208)
        msk[tid] = (tid < NSEQ) ? mask[(size_t)b*NSEQ + tid] : 0.f;
    __syncthreads();

    __half* Oh = O + (size_t)b*NSEQ*CDIM + h*HD;
    for (int mt = warp; mt < 13; mt += 8){
        int m0 = mt*16;
        unsigned af[4][4];
#pragma unroll
        for (int ks=0; ks<4; ks++){
            int kb = ks*16 + 2*tg;
            af[ks][0] = *(const unsigned*)&Qs[(m0+gid  )*72 + kb  ];
            af[ks][1] = *(const unsigned*)&Qs[(m0+gid+8)*72 + kb  ];
            af[ks][2] = *(const unsigned*)&Qs[(m0+gid  )*72 + kb+8];
            af[ks][3] = *(const unsigned*)&Qs[(m0+gid+8)*72 + kb+8];
        }
        float accO[8][4];
#pragma unroll
        for (int nt=0;nt<8;nt++)
#pragma unroll
            for (int q2=0;q2<4;q2++) accO[nt][q2]=0.f;
        float m0r = -1e30f, m1r = -1e30f, l0r = 0.f, l1r = 0.f;

        for (int kt = 0; kt < 13; kt++){
            int n0 = kt*16;
            float s[2][4];
#pragma unroll
            for (int t2=0; t2<2; t2++){
                float a4[4] = {0.f,0.f,0.f,0.f};
#pragma unroll
                for (int ks=0; ks<4; ks++){
                    int kb = ks*16 + 2*tg;
                    unsigned bb[2];
                    bb[0] = *(const unsigned*)&Ks[(n0+t2*8+gid)*72 + kb  ];
                    bb[1] = *(const unsigned*)&Ks[(n0+t2*8+gid)*72 + kb+8];
                    mma_fp16(a4, af[ks], bb);
                }
                int c0 = n0 + t2*8 + 2*tg;
                s[t2][0] = (c0   < NSEQ) ? a4[0]*0.125f : -1e30f;
                s[t2][1] = (c0+1 < NSEQ) ? a4[1]*0.125f : -1e30f;
                s[t2][2] = (c0   < NSEQ) ? a4[2]*0.125f : -1e30f;
                s[t2][3] = (c0+1 < NSEQ) ? a4[3]*0.125f : -1e30f;
            }
            float tm0 = fmaxf(fmaxf(s[0][0], s[0][1]), fmaxf(s[1][0], s[1][1]));
            float tm1 = fmaxf(fmaxf(s[0][2], s[0][3]), fmaxf(s[1][2], s[1][3]));
            tm0 = fmaxf(tm0, __shfl_xor_sync(0xffffffffu, tm0, 1));
            tm0 = fmaxf(tm0, __shfl_xor_sync(0xffffffffu, tm0, 2));
            tm1 = fmaxf(tm1, __shfl_xor_sync(0xffffffffu, tm1, 1));
            tm1 = fmaxf(tm1, __shfl_xor_sync(0xffffffffu, tm1, 2));
            float mn0 = fmaxf(m0r, tm0), mn1 = fmaxf(m1r, tm1);
            float sc0 = __expf(m0r - mn0), sc1 = __expf(m1r - mn1);
            float p[2][4];
#pragma unroll
            for (int t2=0; t2<2; t2++){
                p[t2][0] = __expf(s[t2][0] - mn0);
                p[t2][1] = __expf(s[t2][1] - mn0);
                p[t2][2] = __expf(s[t2][2] - mn1);
                p[t2][3] = __expf(s[t2][3] - mn1);
            }
            float ls0 = p[0][0]+p[0][1]+p[1][0]+p[1][1];
            float ls1 = p[0][2]+p[0][3]+p[1][2]+p[1][3];
            ls0 += __shfl_xor_sync(0xffffffffu, ls0, 1);
            ls0 += __shfl_xor_sync(0xffffffffu, ls0, 2);
            ls1 += __shfl_xor_sync(0xffffffffu, ls1, 1);
            ls1 += __shfl_xor_sync(0xffffffffu, ls1, 2);
            l0r = l0r*sc0 + ls0;
            l1r = l1r*sc1 + ls1;
            m0r = mn0; m1r = mn1;
#pragma unroll
            for (int nt=0; nt<8; nt++){
                accO[nt][0]*=sc0; accO[nt][1]*=sc0;
                accO[nt][2]*=sc1; accO[nt][3]*=sc1;
            }
            unsigned ap[4];
            if (USE_MASK){
                int c0 = n0 + 2*tg, c1 = n0 + 8 + 2*tg;
                float mk00 = msk[c0], mk01 = msk[c0+1];
                float mk10 = msk[c1], mk11 = msk[c1+1];
                __half2 h0 = __floats2half2_rn(p[0][0]*mk00, p[0][1]*mk01);
                __half2 h1 = __floats2half2_rn(p[0][2]*mk00, p[0][3]*mk01);
                __half2 h2 = __floats2half2_rn(p[1][0]*mk10, p[1][1]*mk11);
                __half2 h3 = __floats2half2_rn(p[1][2]*mk10, p[1][3]*mk11);
                ap[0]=*(unsigned*)&h0; ap[1]=*(unsigned*)&h1;
                ap[2]=*(unsigned*)&h2; ap[3]=*(unsigned*)&h3;
            } else {
                __half2 h0 = __floats2half2_rn(p[0][0], p[0][1]);
                __half2 h1 = __floats2half2_rn(p[0][2], p[0][3]);
                __half2 h2 = __floats2half2_rn(p[1][0], p[1][1]);
                __half2 h3 = __floats2half2_rn(p[1][2], p[1][3]);
                ap[0]=*(unsigned*)&h0; ap[1]=*(unsigned*)&h1;
                ap[2]=*(unsigned*)&h2; ap[3]=*(unsigned*)&h3;
            }
            int kv = n0 + 2*tg;
#pragma unroll
            for (int nt=0; nt<8; nt++){
                unsigned bb[2];
                bb[0] = *(const unsigned*)&Vs[(nt*8+gid)*216 + kv  ];
                bb[1] = *(const unsigned*)&Vs[(nt*8+gid)*216 + kv+8];
                mma_fp16(accO[nt], ap, bb);
            }
        }
        float inv0 = 1.f/l0r, inv1 = 1.f/l1r;
        int q0 = m0 + gid, q1 = m0 + gid + 8;
        if (q0 < NSEQ){
#pragma unroll
            for (int nt=0; nt<8; nt++)
                *(__half2*)&Oh[(size_t)q0*CDIM + nt*8 + tg*2] =
                    __floats2half2_rn(accO[nt][0]*inv0, accO[nt][1]*inv0);
        }
        if (q1 < NSEQ){
#pragma unroll
            for (int nt=0; nt<8; nt++)
                *(__half2*)&Oh[(size_t)q1*CDIM + nt*8 + tg*2] =
                    __floats2half2_rn(accO[nt][2]*inv1, accO[nt][3]*inv1);
        }
    }
}

// ---------------- head features: 9 rectangle sums per (b,c) ----------------
__launch_bounds__(256)
__global__ void sfeat_kernel(const __half* __restrict__ T, float* __restrict__ SF)
{
    int i = blockIdx.x*256 + threadIdx.x;
    if (i >= NB*CDIM) return;
    int b = i / CDIM, c = i - b*CDIM;
    const __half* base = T + ((size_t)b*NSEQ + 1)*CDIM + c;
    float tot=0.f, r0=0.f, r13=0.f, c0s=0.f, c13s=0.f;
    for (int u=0; u<14; u++) {
        for (int v=0; v<14; v++) {
            float val = __half2float(base[(size_t)(u*14+v)*CDIM]);
            tot += val;
            if (u==0)  r0  += val;
            if (u==13) r13 += val;
            if (v==0)  c0s += val;
            if (v==13) c13s += val;
        }
    }
    float x00 = __half2float(base[0]);
    float x0e = __half2float(base[(size_t)13*CDIM]);
    float xe0 = __half2float(base[(size_t)(13*14)*CDIM]);
    float xee = __half2float(base[(size_t)(13*14+13)*CDIM]);
    float* o = SF + (size_t)b*6912 + c*9;
    for (int dy=0; dy<3; dy++)
        for (int dx=0; dx<3; dx++) {
            float s = tot;
            if (dy==0) s -= r13;
            if (dy==2) s -= r0;
            if (dx==0) s -= c13s;
            if (dx==2) s -= c0s;
            if (dy==0 && dx==0) s += xee;
            if (dy==0 && dx==2) s += xe0;
            if (dy==2 && dx==0) s += x0e;
            if (dy==2 && dx==2) s += x00;
            o[dy*3+dx] = s;
        }
}

// ---------------- logits ----------------
__launch_bounds__(256)
__global__ void head_kernel(const float* __restrict__ SF, const float* __restrict__ W,
                            const float* __restrict__ bias, float* __restrict__ out)
{
    int gw = (blockIdx.x*256 + threadIdx.x) >> 5;
    int lane = threadIdx.x & 31;
    if (gw >= NB*200) return;
    int b = gw / 200, cls = gw - b*200;
    const float* a = SF + (size_t)b*6912;
    const float* w = W + (size_t)cls*6912;
    float s = 0.f;
    for (int k = lane; k < 6912; k += 32) s = fmaf(a[k], w[k], s);
#pragma unroll
    for (int o=16;o;o>>=1) s += __shfl_xor_sync(0xffffffffu, s, o);
    if (lane==0) out[gw] = s*(1.f/196.f) + bias[cls];
}

// ---------------- final mask outputs ----------------
__launch_bounds__(256)
__global__ void final_mask(const float* __restrict__ Mlayers, const float* __restrict__ gk,
                           float* __restrict__ out)
{
    int b = blockIdx.x;
    __shared__ float ma[196];
    __shared__ float red[8];
    int tid = threadIdx.x;
    if (tid < 196) {
        float s = 0.f;
        for (int l=9; l<12; l++) s += Mlayers[((size_t)l*NB + b)*NSEQ + 1 + tid];
        ma[tid] = s * (1.f/3.f);
    }
    __syncthreads();
    float part = (tid < 196) ? ma[tid] : 0.f;
#pragma unroll
    for (int o=16;o;o>>=1) part += __shfl_xor_sync(0xffffffffu, part, o);
    if ((tid&31)==0) red[tid>>5] = part;
    __syncthreads();
    if (tid==0){ float t=0.f; for(int i=0;i<8;i++) t+=red[i]; out[12800 + b] = t*(1.f/196.f); }
    float t3 = 0.f;
    if (tid < 196) {
        int y = tid/14, x = tid - y*14;
        float m = 0.f;
        for (int dy=0; dy<3; dy++)
            for (int dx=0; dx<3; dx++) {
                int yy = y+dy-1, xx = x+dx-1;
                if (yy>=0 && yy<14 && xx>=0 && xx<14)
                    m += gk[dy*3+dx]*ma[yy*14+xx];
            }
        t3 = (1.f - m)*m;
    }
    __syncthreads();
#pragma unroll
    for (int o=16;o;o>>=1) t3 += __shfl_xor_sync(0xffffffffu, t3, o);
    if ((tid&31)==0) red[tid>>5] = t3;
    __syncthreads();
    if (tid==0){ float t=0.f; for(int i=0;i<8;i++) t+=red[i]; out[12864 + b] = t*(1.f/196.f); }
}

// ---------------- launch ----------------
extern "C" void kernel_launch(void* const* d_in, const int* in_sizes, int n_in,
                              void* d_out, int out_size)
{
    const float* x       = (const float*)d_in[0];
    const float* patch_w = (const float*)d_in[1];
    const float* patch_b = (const float*)d_in[2];
    const float* cls_tok = (const float*)d_in[3];
    const float* loc_tok = (const float*)d_in[4];
    const float* pos_emb = (const float*)d_in[5];
    const float* loc_emb = (const float*)d_in[6];
    const float* ln1_w   = (const float*)d_in[7];
    const float* ln1_b   = (const float*)d_in[8];
    const float* qkv_w   = (const float*)d_in[9];
    const float* proj_w  = (const float*)d_in[10];
    const float* proj_b  = (const float*)d_in[11];
    const float* ln2_w   = (const float*)d_in[12];
    const float* ln2_b   = (const float*)d_in[13];
    const float* fc1_w   = (const float*)d_in[14];
    const float* fc1_b   = (const float*)d_in[15];
    const float* fc2_w   = (const float*)d_in[16];
    const float* fc2_b   = (const float*)d_in[17];
    const float* norm_w  = (const float*)d_in[18];
    const float* norm_b  = (const float*)d_in[19];
    const float* head_w  = (const float*)d_in[20];
    const float* head_b  = (const float*)d_in[21];
    const float* gk      = (const float*)d_in[22];
    float* out = (float*)d_out;

    float *t, *maskb, *sfeat;
    __half *ah, *qkvh, *oh, *hh, *wh;
    cudaGetSymbolAddress((void**)&t,     g_t);
    cudaGetSymbolAddress((void**)&maskb, g_mask);
    cudaGetSymbolAddress((void**)&sfeat, g_sfeat);
    cudaGetSymbolAddress((void**)&ah,    g_ah);
    cudaGetSymbolAddress((void**)&qkvh,  g_qkvh);
    cudaGetSymbolAddress((void**)&oh,    g_oh);
    cudaGetSymbolAddress((void**)&hh,    g_hh);
    cudaGetSymbolAddress((void**)&wh,    g_wh);

    cudaFuncSetAttribute(attn_flash<0>, cudaFuncAttributeMaxDynamicSharedMemorySize, ATT_SMEM);
    cudaFuncSetAttribute(attn_flash<1>, cudaFuncAttributeMaxDynamicSharedMemorySize, ATT_SMEM);
    cudaFuncSetAttribute(gemm_h2<EP_PATCH,float>,      cudaFuncAttributeMaxDynamicSharedMemorySize, G_SMEM);
    cudaFuncSetAttribute(gemm_h2<EP_NONE,__half>,      cudaFuncAttributeMaxDynamicSharedMemorySize, G_SMEM);
    cudaFuncSetAttribute(gemm_h2<EP_BIAS_RES,float>,   cudaFuncAttributeMaxDynamicSharedMemorySize, G_SMEM);
    cudaFuncSetAttribute(gemm_h2<EP_BIAS_GELU,__half>, cudaFuncAttributeMaxDynamicSharedMemorySize, G_SMEM);

    // convert all weights to fp16 pool in one launch
    f2h_all<<<(R_FC2+255)/256, 256>>>(patch_w, qkv_w, proj_w, fc1_w, fc2_w, wh);

    // patch embed: im2col -> GEMM with fused bias+pos+scatter into t; cls/loc rows separate
    im2col_patch<<<(NPAT*CDIM+255)/256, 256>>>(x, ah);
    cls_loc_rows<<<(NB*2*CDIM+255)/256, 256>>>(cls_tok, loc_tok, pos_emb, loc_emb, t);
    gemm_h2<EP_PATCH,float><<<dim3(6,98), 256, G_SMEM>>>(ah, wh + W_PATCH, patch_b, pos_emb,
                                                         t, NPAT, CDIM, CDIM);

    for (int d=0; d<12; d++) {
        ln_kernel<<<NTOK/8, 256>>>(t, ln1_w + d*CDIM, ln1_b + d*CDIM, ah);
        gemm_h2<EP_NONE,__half><<<dim3(18,99), 256, G_SMEM>>>(ah, wh + W_QKV + (size_t)d*3*CDIM*CDIM,
                                                              nullptr, nullptr, qkvh, NTOK, 3*CDIM, CDIM);
        if (d >= 9){
            mask_pre<<<NB, 256>>>(qkvh, maskb + (size_t)d*NB*NSEQ);
            attn_flash<1><<<NB*NHEAD, 256, ATT_SMEM>>>(qkvh, maskb + (size_t)d*NB*NSEQ, oh);
        } else {
            attn_flash<0><<<NB*NHEAD, 256, ATT_SMEM>>>(qkvh, nullptr, oh);
        }
        gemm_h2<EP_BIAS_RES,float><<<dim3(6,99), 256, G_SMEM>>>(oh, wh + W_PROJ + (size_t)d*CDIM*CDIM,
                                                                proj_b + d*CDIM, t, t, NTOK, CDIM, CDIM);
        ln_kernel<<<NTOK/8, 256>>>(t, ln2_w + d*CDIM, ln2_b + d*CDIM, ah);
        gemm_h2<EP_BIAS_GELU,__half><<<dim3(24,99), 256, G_SMEM>>>(ah, wh + W_FC1 + (size_t)d*4*CDIM*CDIM,
                                                                   fc1_b + d*4*CDIM, nullptr, hh, NTOK, 4*CDIM, CDIM);
        gemm_h2<EP_BIAS_RES,float><<<dim3(6,99), 256, G_SMEM>>>(hh, wh + W_FC2 + (size_t)d*CDIM*4*CDIM,
                                                                fc2_b + d*CDIM, t, t, NTOK, CDIM, 4*CDIM);
    }

    ln_kernel<<<NTOK/8, 256>>>(t, norm_w, norm_b, ah);
    sfeat_kernel<<<(NB*CDIM+255)/256, 256>>>(ah, sfeat);
    head_kernel<<<(NB*200*32+255)/256, 256>>>(sfeat, head_w, head_b, out);
    final_mask<<<NB, 256>>>(maskb, gk, out);
}